// round 4
// baseline (speedup 1.0000x reference)
#include <cuda_runtime.h>

#define VOCAB 32000
#define EDIM  128
#define HDIM  256
#define NBATCH 8
#define SEQ   512
#define MTOT  (NBATCH * SEQ)   // 4096
#define G3    (3 * HDIM)       // 768

// ---- scratch (static device globals; no allocation) ----
__device__ float    g_gi[MTOT * G3];        // [4096, 768] input-side gate preacts
__device__ float    g_hidden[MTOT * HDIM];  // [4096, 256] GRU outputs
__device__ float    g_hbuf[2][NBATCH][HDIM];
__device__ unsigned g_sync;

// ---- packed f32x2 helpers (Blackwell sm_103a) ----
__device__ __forceinline__ unsigned long long f2_pack(float x, float y) {
    unsigned long long r;
    asm("mov.b64 %0, {%1, %2};" : "=l"(r) : "f"(x), "f"(y));
    return r;
}
__device__ __forceinline__ unsigned long long f2_fma(unsigned long long a,
                                                     unsigned long long b,
                                                     unsigned long long c) {
    unsigned long long d;
    asm("fma.rn.f32x2 %0, %1, %2, %3;" : "=l"(d) : "l"(a), "l"(b), "l"(c));
    return d;
}
__device__ __forceinline__ unsigned long long f2_add(unsigned long long a,
                                                     unsigned long long b) {
    unsigned long long d;
    asm("add.rn.f32x2 %0, %1, %2;" : "=l"(d) : "l"(a), "l"(b));
    return d;
}

// =====================================================================
// Kernel A: gi[m][g] = sum_e emb[t[m]][e] * w_ih[g][e] + b_ih[g]
// M=4096, N=768, K=128. 64x64 tiles, K chunks of 32. Also resets g_sync.
// =====================================================================
__global__ void __launch_bounds__(256)
embed_gi_kernel(const int* __restrict__ t,
                const float* __restrict__ emb,
                const float* __restrict__ w_ih,
                const float* __restrict__ b_ih) {
    if (blockIdx.x == 0 && blockIdx.y == 0 && threadIdx.x == 0) g_sync = 0u;

    __shared__ float As[32][64];
    __shared__ float Bs[32][64];
    __shared__ int   tok[64];

    int tid = threadIdx.x;
    int m0 = blockIdx.y * 64;
    int n0 = blockIdx.x * 64;

    if (tid < 64) tok[tid] = t[m0 + tid];
    __syncthreads();

    int tm = tid >> 4;   // 0..15
    int tn = tid & 15;   // 0..15
    float c[4][4];
#pragma unroll
    for (int i = 0; i < 4; i++)
#pragma unroll
        for (int j = 0; j < 4; j++) c[i][j] = 0.f;

    for (int kc = 0; kc < EDIM; kc += 32) {
#pragma unroll
        for (int r = 0; r < 2; r++) {
            int f   = tid + 256 * r;    // 0..511
            int row = f >> 3;           // 0..63
            int c4  = f & 7;            // 0..7
            float4 av = *reinterpret_cast<const float4*>(
                &emb[(size_t)tok[row] * EDIM + kc + c4 * 4]);
            As[c4 * 4 + 0][row] = av.x; As[c4 * 4 + 1][row] = av.y;
            As[c4 * 4 + 2][row] = av.z; As[c4 * 4 + 3][row] = av.w;
            float4 bv = *reinterpret_cast<const float4*>(
                &w_ih[(size_t)(n0 + row) * EDIM + kc + c4 * 4]);
            Bs[c4 * 4 + 0][row] = bv.x; Bs[c4 * 4 + 1][row] = bv.y;
            Bs[c4 * 4 + 2][row] = bv.z; Bs[c4 * 4 + 3][row] = bv.w;
        }
        __syncthreads();
#pragma unroll
        for (int k = 0; k < 32; k++) {
            float a[4], b[4];
#pragma unroll
            for (int i = 0; i < 4; i++) a[i] = As[k][tm * 4 + i];
#pragma unroll
            for (int j = 0; j < 4; j++) b[j] = Bs[k][tn * 4 + j];
#pragma unroll
            for (int i = 0; i < 4; i++)
#pragma unroll
                for (int j = 0; j < 4; j++) c[i][j] += a[i] * b[j];
        }
        __syncthreads();
    }

#pragma unroll
    for (int i = 0; i < 4; i++) {
        int m = m0 + tm * 4 + i;
#pragma unroll
        for (int j = 0; j < 4; j++) {
            int n = n0 + tn * 4 + j;
            g_gi[(size_t)m * G3 + n] = c[i][j] + b_ih[n];
        }
    }
}

// =====================================================================
// Kernel B: GRU recurrence, persistent grid with software grid sync.
// 64 blocks x 384 threads. Block owns 4 hidden units (12 gate rows).
// Each thread: one (row, batch) dot, k-split 4 ways; w_hh slice in regs.
// =====================================================================
#define GRU_NBLK 64
#define GRU_TPB  384
#define HPAD     264   // padded h row stride in smem (bank-friendly)

__global__ void __launch_bounds__(GRU_TPB, 1)
gru_kernel(const float* __restrict__ h0,
           const float* __restrict__ w_hh,
           const float* __restrict__ b_hh) {
    int tid = threadIdx.x;
    int blk = blockIdx.x;

    int d  = tid >> 2;       // 0..95  : which (row, batch) dot
    int ks = tid & 3;        // 0..3   : k-slice
    int lr = d % 12;         // local gate row 0..11
    int b  = d / 12;         // batch 0..7
    int gate = lr >> 2;      // 0..2  (r, z, n)
    int u    = lr & 3;       // 0..3
    int ug   = blk * 4 + u;          // global hidden unit
    int grow = gate * HDIM + ug;     // global gate row in w_hh

    // cache this thread's 64-float slice of w_hh row in registers
    float4 w[16];
#pragma unroll
    for (int j = 0; j < 16; j++)
        w[j] = *reinterpret_cast<const float4*>(
            &w_hh[(size_t)grow * HDIM + (j * 4 + ks) * 4]);
    float bias = b_hh[grow];

    __shared__ __align__(16) float h_s[NBATCH * HPAD];
    __shared__ float gh_s[12][8];

    int cu = tid >> 3;   // for combine threads (tid<32): unit 0..3
    int cb = tid & 7;    // batch 0..7

    // init h buffer (broadcast h0 over batch)
    if (tid < 32) g_hbuf[0][cb][blk * 4 + cu] = h0[blk * 4 + cu];
    __threadfence();
    __syncthreads();
    if (tid == 0) atomicAdd(&g_sync, 1u);
    unsigned target = GRU_NBLK;
    if (tid == 0) { while (*(volatile unsigned*)&g_sync < target) {} }
    __syncthreads();

    for (int s = 0; s < SEQ; s++) {
        int p = s & 1;

        // prefetch input-side gate preacts for the combine phase
        float gir = 0.f, giz = 0.f, gin = 0.f;
        if (tid < 32) {
            size_t m = (size_t)cb * SEQ + s;
            const float* gim = &g_gi[m * G3 + blk * 4 + cu];
            gir = __ldg(gim);
            giz = __ldg(gim + HDIM);
            gin = __ldg(gim + 2 * HDIM);
        }

        // stage h (written by other SMs -> must bypass L1)
        const float* hb = &g_hbuf[p][0][0];
        for (int i = tid; i < NBATCH * HDIM; i += GRU_TPB)
            h_s[(i >> 8) * HPAD + (i & 255)] = __ldcg(hb + i);
        __syncthreads();

        // partial dot over this thread's 64-element k-slice
        float a0 = 0.f, a1 = 0.f, a2 = 0.f, a3 = 0.f;
        const float* hr = &h_s[b * HPAD];
#pragma unroll
        for (int j = 0; j < 16; j++) {
            float4 hv = *reinterpret_cast<const float4*>(&hr[(j * 4 + ks) * 4]);
            a0 += w[j].x * hv.x;
            a1 += w[j].y * hv.y;
            a2 += w[j].z * hv.z;
            a3 += w[j].w * hv.w;
        }
        float acc = (a0 + a1) + (a2 + a3);
        acc += __shfl_xor_sync(0xffffffffu, acc, 1);
        acc += __shfl_xor_sync(0xffffffffu, acc, 2);
        if (ks == 0) gh_s[lr][b] = acc + bias;
        __syncthreads();

        // combine gates, write new h
        if (tid < 32) {
            float hrv  = gh_s[cu][cb];
            float hzv  = gh_s[4 + cu][cb];
            float hnv  = gh_s[8 + cu][cb];
            float hold = h_s[cb * HPAD + blk * 4 + cu];
            float r = 1.f / (1.f + __expf(-(gir + hrv)));
            float z = 1.f / (1.f + __expf(-(giz + hzv)));
            float n = tanhf(gin + r * hnv);
            float hnew = (1.f - z) * n + z * hold;
            g_hbuf[p ^ 1][cb][blk * 4 + cu] = hnew;
            g_hidden[((size_t)cb * SEQ + s) * HDIM + blk * 4 + cu] = hnew;
        }
        __threadfence();
        __syncthreads();
        if (tid == 0) atomicAdd(&g_sync, 1u);
        target += GRU_NBLK;
        if (tid == 0) { while (*(volatile unsigned*)&g_sync < target) {} }
        __syncthreads();
    }
}

// =====================================================================
// Kernel C: out[m][v] = hidden[m] . w_out[v] + b_out[v]
// M=4096, N=32000, K=256. 128x128 tiles, TK=16, 8x8/thread,
// packed fma.rn.f32x2 inner product (2 FLOPs per FMA issue slot).
// =====================================================================
#define CPAD 132

__global__ void __launch_bounds__(256, 2)
out_gemm_kernel(const float* __restrict__ w_out,
                const float* __restrict__ b_out,
                float* __restrict__ out) {
    __shared__ float As[2][16][CPAD];
    __shared__ float Bs[2][16][CPAD];

    int tid = threadIdx.x;
    int m0 = blockIdx.y * 128;
    int n0 = blockIdx.x * 128;

    int lrow = tid >> 2;          // 0..63
    int lc4  = (tid & 3) * 4;     // 0,4,8,12

    const float* a0p = &g_hidden[(size_t)(m0 + lrow) * HDIM + lc4];
    const float* a1p = a0p + (size_t)64 * HDIM;
    const float* b0p = &w_out[(size_t)(n0 + lrow) * HDIM + lc4];
    const float* b1p = b0p + (size_t)64 * HDIM;

    // prologue: stage 0
    {
        float4 xa0 = *reinterpret_cast<const float4*>(a0p);
        float4 xa1 = *reinterpret_cast<const float4*>(a1p);
        float4 xb0 = *reinterpret_cast<const float4*>(b0p);
        float4 xb1 = *reinterpret_cast<const float4*>(b1p);
        As[0][lc4 + 0][lrow] = xa0.x; As[0][lc4 + 1][lrow] = xa0.y;
        As[0][lc4 + 2][lrow] = xa0.z; As[0][lc4 + 3][lrow] = xa0.w;
        As[0][lc4 + 0][lrow + 64] = xa1.x; As[0][lc4 + 1][lrow + 64] = xa1.y;
        As[0][lc4 + 2][lrow + 64] = xa1.z; As[0][lc4 + 3][lrow + 64] = xa1.w;
        Bs[0][lc4 + 0][lrow] = xb0.x; Bs[0][lc4 + 1][lrow] = xb0.y;
        Bs[0][lc4 + 2][lrow] = xb0.z; Bs[0][lc4 + 3][lrow] = xb0.w;
        Bs[0][lc4 + 0][lrow + 64] = xb1.x; Bs[0][lc4 + 1][lrow + 64] = xb1.y;
        Bs[0][lc4 + 2][lrow + 64] = xb1.z; Bs[0][lc4 + 3][lrow + 64] = xb1.w;
    }
    __syncthreads();

    int tm = tid >> 4;   // 0..15
    int tn = tid & 15;   // 0..15

    unsigned long long c2[8][4];
#pragma unroll
    for (int i = 0; i < 8; i++)
#pragma unroll
        for (int j = 0; j < 4; j++) c2[i][j] = 0ull;

    for (int ksg = 0; ksg < 16; ksg++) {
        int buf = ksg & 1;
        float4 na0, na1, nb0, nb1;
        if (ksg < 15) {
            int off = (ksg + 1) * 16;
            na0 = *reinterpret_cast<const float4*>(a0p + off);
            na1 = *reinterpret_cast<const float4*>(a1p + off);
            nb0 = *reinterpret_cast<const float4*>(b0p + off);
            nb1 = *reinterpret_cast<const float4*>(b1p + off);
        }
#pragma unroll
        for (int kk = 0; kk < 16; kk++) {
            const float* ar = &As[buf][kk][tm * 8];
            const float* br = &Bs[buf][kk][tn * 8];
            float4 af0 = *reinterpret_cast<const float4*>(ar);
            float4 af1 = *reinterpret_cast<const float4*>(ar + 4);
            float4 bf0 = *reinterpret_cast<const float4*>(br);
            float4 bf1 = *reinterpret_cast<const float4*>(br + 4);
            unsigned long long bp0 = f2_pack(bf0.x, bf0.y);
            unsigned long long bp1 = f2_pack(bf0.z, bf0.w);
            unsigned long long bp2 = f2_pack(bf1.x, bf1.y);
            unsigned long long bp3 = f2_pack(bf1.z, bf1.w);
            float aa[8] = {af0.x, af0.y, af0.z, af0.w,
                           af1.x, af1.y, af1.z, af1.w};
#pragma unroll
            for (int i = 0; i < 8; i++) {
                unsigned long long ap = f2_pack(aa[i], aa[i]);
                c2[i][0] = f2_fma(ap, bp0, c2[i][0]);
                c2[i][1] = f2_fma(ap, bp1, c2[i][1]);
                c2[i][2] = f2_fma(ap, bp2, c2[i][2]);
                c2[i][3] = f2_fma(ap, bp3, c2[i][3]);
            }
        }
        if (ksg < 15) {
            __syncthreads();
            int nb = buf ^ 1;
            As[nb][lc4 + 0][lrow] = na0.x; As[nb][lc4 + 1][lrow] = na0.y;
            As[nb][lc4 + 2][lrow] = na0.z; As[nb][lc4 + 3][lrow] = na0.w;
            As[nb][lc4 + 0][lrow + 64] = na1.x; As[nb][lc4 + 1][lrow + 64] = na1.y;
            As[nb][lc4 + 2][lrow + 64] = na1.z; As[nb][lc4 + 3][lrow + 64] = na1.w;
            Bs[nb][lc4 + 0][lrow] = nb0.x; Bs[nb][lc4 + 1][lrow] = nb0.y;
            Bs[nb][lc4 + 2][lrow] = nb0.z; Bs[nb][lc4 + 3][lrow] = nb0.w;
            Bs[nb][lc4 + 0][lrow + 64] = nb1.x; Bs[nb][lc4 + 1][lrow + 64] = nb1.y;
            Bs[nb][lc4 + 2][lrow + 64] = nb1.z; Bs[nb][lc4 + 3][lrow + 64] = nb1.w;
            __syncthreads();
        }
    }

    // epilogue: add bias (packed), store 8 rows x 8 cols
    float4 bb0 = *reinterpret_cast<const float4*>(&b_out[n0 + tn * 8]);
    float4 bb1 = *reinterpret_cast<const float4*>(&b_out[n0 + tn * 8 + 4]);
    unsigned long long bo[4] = {f2_pack(bb0.x, bb0.y), f2_pack(bb0.z, bb0.w),
                                f2_pack(bb1.x, bb1.y), f2_pack(bb1.z, bb1.w)};
#pragma unroll
    for (int i = 0; i < 8; i++) {
        union { unsigned long long u[4]; float4 f[2]; } r;
        r.u[0] = f2_add(c2[i][0], bo[0]);
        r.u[1] = f2_add(c2[i][1], bo[1]);
        r.u[2] = f2_add(c2[i][2], bo[2]);
        r.u[3] = f2_add(c2[i][3], bo[3]);
        float* orow = &out[(size_t)(m0 + tm * 8 + i) * VOCAB + n0 + tn * 8];
        *reinterpret_cast<float4*>(orow)     = r.f[0];
        *reinterpret_cast<float4*>(orow + 4) = r.f[1];
    }
}

// =====================================================================
// launch
// =====================================================================
extern "C" void kernel_launch(void* const* d_in, const int* in_sizes, int n_in,
                              void* d_out, int out_size) {
    const int*   t     = (const int*)d_in[0];
    const float* emb   = (const float*)d_in[1];
    const float* h0    = (const float*)d_in[2];
    const float* w_ih  = (const float*)d_in[3];
    const float* w_hh  = (const float*)d_in[4];
    const float* b_ih  = (const float*)d_in[5];
    const float* b_hh  = (const float*)d_in[6];
    const float* w_out = (const float*)d_in[7];
    const float* b_out = (const float*)d_in[8];
    float* out = (float*)d_out;

    embed_gi_kernel<<<dim3(G3 / 64, MTOT / 64), 256>>>(t, emb, w_ih, b_ih);
    gru_kernel<<<GRU_NBLK, GRU_TPB>>>(h0, w_hh, b_hh);
    out_gemm_kernel<<<dim3(VOCAB / 128, MTOT / 128), 256>>>(w_out, b_out, out);
}

// round 6
// speedup vs baseline: 1.5331x; 1.5331x over previous
#include <cuda_runtime.h>

#define VOCAB 32000
#define EDIM  128
#define HDIM  256
#define NBATCH 8
#define SEQ   512
#define MTOT  (NBATCH * SEQ)   // 4096
#define G3    (3 * HDIM)       // 768

// ---- scratch (static device globals; no allocation) ----
__device__ float g_gi[MTOT * G3];                       // [4096, 768] input gate preacts
__device__ float g_hidden[MTOT * HDIM];                 // [4096, 256] GRU outputs
__device__ unsigned long long g_htag[2][NBATCH][HDIM];  // (tag<<32)|float bits

// ---- packed f32x2 helpers (Blackwell sm_103a) ----
__device__ __forceinline__ unsigned long long f2_pack(float x, float y) {
    unsigned long long r;
    asm("mov.b64 %0, {%1, %2};" : "=l"(r) : "f"(x), "f"(y));
    return r;
}
__device__ __forceinline__ unsigned long long f2_fma(unsigned long long a,
                                                     unsigned long long b,
                                                     unsigned long long c) {
    unsigned long long d;
    asm("fma.rn.f32x2 %0, %1, %2, %3;" : "=l"(d) : "l"(a), "l"(b), "l"(c));
    return d;
}
__device__ __forceinline__ unsigned long long f2_add(unsigned long long a,
                                                     unsigned long long b) {
    unsigned long long d;
    asm("add.rn.f32x2 %0, %1, %2;" : "=l"(d) : "l"(a), "l"(b));
    return d;
}
__device__ __forceinline__ void f2_unpack(unsigned long long v, float& lo, float& hi) {
    asm("mov.b64 {%0, %1}, %2;" : "=f"(lo), "=f"(hi) : "l"(v));
}
// ---- formally-atomic 64-bit tag word ops (gpu scope, L2 coherent) ----
__device__ __forceinline__ unsigned long long ld_rlx64(const unsigned long long* p) {
    unsigned long long v;
    asm volatile("ld.relaxed.gpu.global.b64 %0, [%1];" : "=l"(v) : "l"(p) : "memory");
    return v;
}
__device__ __forceinline__ void st_rlx64(unsigned long long* p, unsigned long long v) {
    asm volatile("st.relaxed.gpu.global.b64 [%0], %1;" :: "l"(p), "l"(v) : "memory");
}

// =====================================================================
// Kernel A: gi = emb[t] @ w_ih^T + b_ih (M=4096,N=768,K=128).
// Block (0,0) also zeroes the h tag buffer (kills cross-replay stale tags).
// =====================================================================
__global__ void __launch_bounds__(256)
embed_gi_kernel(const int* __restrict__ t,
                const float* __restrict__ emb,
                const float* __restrict__ w_ih,
                const float* __restrict__ b_ih) {
    int tid = threadIdx.x;
    if (blockIdx.x == 0 && blockIdx.y == 0) {
        unsigned long long* p = &g_htag[0][0][0];
        for (int i = tid; i < 2 * NBATCH * HDIM; i += 256) p[i] = 0ull;
    }

    __shared__ float As[32][64];
    __shared__ float Bs[32][64];
    __shared__ int   tok[64];

    int m0 = blockIdx.y * 64;
    int n0 = blockIdx.x * 64;

    if (tid < 64) tok[tid] = t[m0 + tid];
    __syncthreads();

    int tm = tid >> 4;
    int tn = tid & 15;
    float c[4][4];
#pragma unroll
    for (int i = 0; i < 4; i++)
#pragma unroll
        for (int j = 0; j < 4; j++) c[i][j] = 0.f;

    for (int kc = 0; kc < EDIM; kc += 32) {
#pragma unroll
        for (int r = 0; r < 2; r++) {
            int f   = tid + 256 * r;
            int row = f >> 3;
            int c4  = f & 7;
            float4 av = *reinterpret_cast<const float4*>(
                &emb[(size_t)tok[row] * EDIM + kc + c4 * 4]);
            As[c4 * 4 + 0][row] = av.x; As[c4 * 4 + 1][row] = av.y;
            As[c4 * 4 + 2][row] = av.z; As[c4 * 4 + 3][row] = av.w;
            float4 bv = *reinterpret_cast<const float4*>(
                &w_ih[(size_t)(n0 + row) * EDIM + kc + c4 * 4]);
            Bs[c4 * 4 + 0][row] = bv.x; Bs[c4 * 4 + 1][row] = bv.y;
            Bs[c4 * 4 + 2][row] = bv.z; Bs[c4 * 4 + 3][row] = bv.w;
        }
        __syncthreads();
#pragma unroll
        for (int k = 0; k < 32; k++) {
            float a[4], b[4];
#pragma unroll
            for (int i = 0; i < 4; i++) a[i] = As[k][tm * 4 + i];
#pragma unroll
            for (int j = 0; j < 4; j++) b[j] = Bs[k][tn * 4 + j];
#pragma unroll
            for (int i = 0; i < 4; i++)
#pragma unroll
                for (int j = 0; j < 4; j++) c[i][j] += a[i] * b[j];
        }
        __syncthreads();
    }

#pragma unroll
    for (int i = 0; i < 4; i++) {
        int m = m0 + tm * 4 + i;
#pragma unroll
        for (int j = 0; j < 4; j++) {
            int n = n0 + tn * 4 + j;
            g_gi[(size_t)m * G3 + n] = c[i][j] + b_ih[n];
        }
    }
}

// =====================================================================
// Kernel B: GRU recurrence, barrier-free via self-tagged h words.
// 64 blocks = 8 batches x 8 unit-groups (32 units). 384 threads:
// thread = (gate-row lr 0..95) x (k-slice ks 0..3), w_hh slice in regs.
// Tag words are relaxed-atomic 64-bit (tag<<32 | float) so tag and data
// can never tear. 'hold' (previous h of own unit) is carried in a
// register by the combine warp -> no unsynchronized h_s reads remain.
// =====================================================================
#define GRU_NBLK 64
#define GRU_TPB  384

__global__ void __launch_bounds__(GRU_TPB, 1)
gru_kernel(const float* __restrict__ h0,
           const float* __restrict__ w_hh,
           const float* __restrict__ b_hh) {
    int tid = threadIdx.x;
    int blk = blockIdx.x;
    int b   = blk >> 3;      // batch 0..7
    int g   = blk & 7;       // unit group 0..7 (32 units each)

    int lr = tid >> 2;       // local gate row 0..95
    int ks = tid & 3;        // k-slice 0..3
    int gate = lr >> 5;      // 0..2
    int u    = lr & 31;      // 0..31
    int grow = gate * HDIM + g * 32 + u;
    int lane = tid & 31;

    // this thread's 64-float w_hh slice, packed for f32x2
    unsigned long long w2[32];
#pragma unroll
    for (int j = 0; j < 16; j++) {
        float4 wv = *reinterpret_cast<const float4*>(
            &w_hh[(size_t)grow * HDIM + (j * 4 + ks) * 4]);
        w2[2 * j]     = f2_pack(wv.x, wv.y);
        w2[2 * j + 1] = f2_pack(wv.z, wv.w);
    }
    float bias = b_hh[grow];

    __shared__ __align__(16) float h_s[HDIM];
    __shared__ float gh_s[96];

    // combine warp carries its own unit's h in a register
    float hold = 0.f;
    if (tid < 32) {
        hold = h0[g * 32 + lane];
        unsigned long long word =
            (1ull << 32) | (unsigned long long)__float_as_uint(hold);
        st_rlx64(&g_htag[0][b][g * 32 + lane], word);
    }

    for (int s = 0; s < SEQ; s++) {
        int p = s & 1;
        unsigned want = (unsigned)(s + 1);

        // prefetch input-side gate preacts (combine warp)
        float gir = 0.f, giz = 0.f, gin = 0.f;
        if (tid < 32) {
            size_t m = (size_t)b * SEQ + s;
            const float* gm = &g_gi[m * G3 + g * 32 + lane];
            gir = __ldg(gm);
            giz = __ldg(gm + HDIM);
            gin = __ldg(gm + 2 * HDIM);
        }

        // poll self-tagged h words for this step (one word per thread).
        // tag and payload live in one atomic 64-bit word -> no ordering
        // beyond the relaxed atomic load is required.
        if (tid < HDIM) {
            const unsigned long long* wp = &g_htag[p][b][tid];
            unsigned long long v = ld_rlx64(wp);
            while ((unsigned)(v >> 32) != want) v = ld_rlx64(wp);
            h_s[tid] = __uint_as_float((unsigned)v);
        }
        __syncthreads();

        // partial dot over 64-element k-slice (packed f32x2)
        unsigned long long acc0 = 0ull, acc1 = 0ull;
        const ulonglong2* hp = reinterpret_cast<const ulonglong2*>(h_s);
#pragma unroll
        for (int j = 0; j < 16; j++) {
            ulonglong2 hv = hp[j * 4 + ks];
            acc0 = f2_fma(w2[2 * j],     hv.x, acc0);
            acc1 = f2_fma(w2[2 * j + 1], hv.y, acc1);
        }
        float a0, a1, a2, a3;
        f2_unpack(acc0, a0, a1);
        f2_unpack(acc1, a2, a3);
        float acc = (a0 + a1) + (a2 + a3);
        acc += __shfl_xor_sync(0xffffffffu, acc, 1);
        acc += __shfl_xor_sync(0xffffffffu, acc, 2);
        if (ks == 0) gh_s[lr] = acc + bias;
        __syncthreads();

        // combine gates, publish tagged h_{s+1} (hold is register-carried)
        if (tid < 32) {
            float hrv = gh_s[lane];
            float hzv = gh_s[32 + lane];
            float hnv = gh_s[64 + lane];
            float r = 1.f / (1.f + __expf(-(gir + hrv)));
            float z = 1.f / (1.f + __expf(-(giz + hzv)));
            float n = tanhf(gin + r * hnv);
            float hnew = (1.f - z) * n + z * hold;
            hold = hnew;
            g_hidden[((size_t)b * SEQ + s) * HDIM + g * 32 + lane] = hnew;
            unsigned long long word =
                ((unsigned long long)(unsigned)(s + 2) << 32) |
                (unsigned long long)__float_as_uint(hnew);
            st_rlx64(&g_htag[p ^ 1][b][g * 32 + lane], word);
        }
        // no block barrier needed: every h_s overwrite in the next
        // iteration is gated on fresh tags, and gh_s rewrites happen
        // only after the next iteration's first __syncthreads.
    }
}

// =====================================================================
// Kernel C: out = hidden @ w_out^T + b_out (M=4096, N=32000, K=256).
// 128x128 tiles, TK=16, 8x8/thread, packed fma.rn.f32x2.
// (round-4 version, verified rel_err 2.7e-7)
// =====================================================================
#define CPAD 132

__global__ void __launch_bounds__(256, 2)
out_gemm_kernel(const float* __restrict__ w_out,
                const float* __restrict__ b_out,
                float* __restrict__ out) {
    __shared__ float As[2][16][CPAD];
    __shared__ float Bs[2][16][CPAD];

    int tid = threadIdx.x;
    int m0 = blockIdx.y * 128;
    int n0 = blockIdx.x * 128;

    int lrow = tid >> 2;          // 0..63
    int lc4  = (tid & 3) * 4;     // 0,4,8,12

    const float* a0p = &g_hidden[(size_t)(m0 + lrow) * HDIM + lc4];
    const float* a1p = a0p + (size_t)64 * HDIM;
    const float* b0p = &w_out[(size_t)(n0 + lrow) * HDIM + lc4];
    const float* b1p = b0p + (size_t)64 * HDIM;

    // prologue: stage 0
    {
        float4 xa0 = *reinterpret_cast<const float4*>(a0p);
        float4 xa1 = *reinterpret_cast<const float4*>(a1p);
        float4 xb0 = *reinterpret_cast<const float4*>(b0p);
        float4 xb1 = *reinterpret_cast<const float4*>(b1p);
        As[0][lc4 + 0][lrow] = xa0.x; As[0][lc4 + 1][lrow] = xa0.y;
        As[0][lc4 + 2][lrow] = xa0.z; As[0][lc4 + 3][lrow] = xa0.w;
        As[0][lc4 + 0][lrow + 64] = xa1.x; As[0][lc4 + 1][lrow + 64] = xa1.y;
        As[0][lc4 + 2][lrow + 64] = xa1.z; As[0][lc4 + 3][lrow + 64] = xa1.w;
        Bs[0][lc4 + 0][lrow] = xb0.x; Bs[0][lc4 + 1][lrow] = xb0.y;
        Bs[0][lc4 + 2][lrow] = xb0.z; Bs[0][lc4 + 3][lrow] = xb0.w;
        Bs[0][lc4 + 0][lrow + 64] = xb1.x; Bs[0][lc4 + 1][lrow + 64] = xb1.y;
        Bs[0][lc4 + 2][lrow + 64] = xb1.z; Bs[0][lc4 + 3][lrow + 64] = xb1.w;
    }
    __syncthreads();

    int tm = tid >> 4;   // 0..15
    int tn = tid & 15;   // 0..15

    unsigned long long c2[8][4];
#pragma unroll
    for (int i = 0; i < 8; i++)
#pragma unroll
        for (int j = 0; j < 4; j++) c2[i][j] = 0ull;

    for (int ksg = 0; ksg < 16; ksg++) {
        int buf = ksg & 1;
        float4 na0, na1, nb0, nb1;
        if (ksg < 15) {
            int off = (ksg + 1) * 16;
            na0 = *reinterpret_cast<const float4*>(a0p + off);
            na1 = *reinterpret_cast<const float4*>(a1p + off);
            nb0 = *reinterpret_cast<const float4*>(b0p + off);
            nb1 = *reinterpret_cast<const float4*>(b1p + off);
        }
#pragma unroll
        for (int kk = 0; kk < 16; kk++) {
            const float* ar = &As[buf][kk][tm * 8];
            const float* br = &Bs[buf][kk][tn * 8];
            float4 af0 = *reinterpret_cast<const float4*>(ar);
            float4 af1 = *reinterpret_cast<const float4*>(ar + 4);
            float4 bf0 = *reinterpret_cast<const float4*>(br);
            float4 bf1 = *reinterpret_cast<const float4*>(br + 4);
            unsigned long long bp0 = f2_pack(bf0.x, bf0.y);
            unsigned long long bp1 = f2_pack(bf0.z, bf0.w);
            unsigned long long bp2 = f2_pack(bf1.x, bf1.y);
            unsigned long long bp3 = f2_pack(bf1.z, bf1.w);
            float aa[8] = {af0.x, af0.y, af0.z, af0.w,
                           af1.x, af1.y, af1.z, af1.w};
#pragma unroll
            for (int i = 0; i < 8; i++) {
                unsigned long long ap = f2_pack(aa[i], aa[i]);
                c2[i][0] = f2_fma(ap, bp0, c2[i][0]);
                c2[i][1] = f2_fma(ap, bp1, c2[i][1]);
                c2[i][2] = f2_fma(ap, bp2, c2[i][2]);
                c2[i][3] = f2_fma(ap, bp3, c2[i][3]);
            }
        }
        if (ksg < 15) {
            __syncthreads();
            int nb = buf ^ 1;
            As[nb][lc4 + 0][lrow] = na0.x; As[nb][lc4 + 1][lrow] = na0.y;
            As[nb][lc4 + 2][lrow] = na0.z; As[nb][lc4 + 3][lrow] = na0.w;
            As[nb][lc4 + 0][lrow + 64] = na1.x; As[nb][lc4 + 1][lrow + 64] = na1.y;
            As[nb][lc4 + 2][lrow + 64] = na1.z; As[nb][lc4 + 3][lrow + 64] = na1.w;
            Bs[nb][lc4 + 0][lrow] = nb0.x; Bs[nb][lc4 + 1][lrow] = nb0.y;
            Bs[nb][lc4 + 2][lrow] = nb0.z; Bs[nb][lc4 + 3][lrow] = nb0.w;
            Bs[nb][lc4 + 0][lrow + 64] = nb1.x; Bs[nb][lc4 + 1][lrow + 64] = nb1.y;
            Bs[nb][lc4 + 2][lrow + 64] = nb1.z; Bs[nb][lc4 + 3][lrow + 64] = nb1.w;
            __syncthreads();
        }
    }

    // epilogue: add bias (packed), store 8 rows x 8 cols
    float4 bb0 = *reinterpret_cast<const float4*>(&b_out[n0 + tn * 8]);
    float4 bb1 = *reinterpret_cast<const float4*>(&b_out[n0 + tn * 8 + 4]);
    unsigned long long bo[4] = {f2_pack(bb0.x, bb0.y), f2_pack(bb0.z, bb0.w),
                                f2_pack(bb1.x, bb1.y), f2_pack(bb1.z, bb1.w)};
#pragma unroll
    for (int i = 0; i < 8; i++) {
        union { unsigned long long u[4]; float4 f[2]; } r;
        r.u[0] = f2_add(c2[i][0], bo[0]);
        r.u[1] = f2_add(c2[i][1], bo[1]);
        r.u[2] = f2_add(c2[i][2], bo[2]);
        r.u[3] = f2_add(c2[i][3], bo[3]);
        float* orow = &out[(size_t)(m0 + tm * 8 + i) * VOCAB + n0 + tn * 8];
        *reinterpret_cast<float4*>(orow)     = r.f[0];
        *reinterpret_cast<float4*>(orow + 4) = r.f[1];
    }
}

// =====================================================================
// launch
// =====================================================================
extern "C" void kernel_launch(void* const* d_in, const int* in_sizes, int n_in,
                              void* d_out, int out_size) {
    const int*   t     = (const int*)d_in[0];
    const float* emb   = (const float*)d_in[1];
    const float* h0    = (const float*)d_in[2];
    const float* w_ih  = (const float*)d_in[3];
    const float* w_hh  = (const float*)d_in[4];
    const float* b_ih  = (const float*)d_in[5];
    const float* b_hh  = (const float*)d_in[6];
    const float* w_out = (const float*)d_in[7];
    const float* b_out = (const float*)d_in[8];
    float* out = (float*)d_out;

    embed_gi_kernel<<<dim3(G3 / 64, MTOT / 64), 256>>>(t, emb, w_ih, b_ih);
    gru_kernel<<<GRU_NBLK, GRU_TPB>>>(h0, w_hh, b_hh);
    out_gemm_kernel<<<dim3(VOCAB / 128, MTOT / 128), 256>>>(w_out, b_out, out);
}

// round 8
// speedup vs baseline: 2.3683x; 1.5448x over previous
#include <cuda_runtime.h>
#include <cuda_bf16.h>
#include <cstdint>

#define VOCAB 32000
#define EDIM  128
#define HDIM  256
#define NBATCH 8
#define SEQ   512
#define MTOT  (NBATCH * SEQ)   // 4096
#define G3    (3 * HDIM)       // 768
#define KP    768              // split K' = 3 * 256

// ---- scratch (static device globals; no allocation) ----
__device__ float g_gi[MTOT * G3];
__device__ float g_hidden[MTOT * HDIM];
__device__ unsigned long long g_htag[2][NBATCH][HDIM];
__device__ __nv_bfloat16 g_A2[(size_t)MTOT * KP];    // [4096][768]
__device__ __nv_bfloat16 g_B2[(size_t)VOCAB * KP];   // [32000][768]

// ---- packed f32x2 helpers ----
__device__ __forceinline__ unsigned long long f2_pack(float x, float y) {
    unsigned long long r;
    asm("mov.b64 %0, {%1, %2};" : "=l"(r) : "f"(x), "f"(y));
    return r;
}
__device__ __forceinline__ unsigned long long f2_fma(unsigned long long a,
                                                     unsigned long long b,
                                                     unsigned long long c) {
    unsigned long long d;
    asm("fma.rn.f32x2 %0, %1, %2, %3;" : "=l"(d) : "l"(a), "l"(b), "l"(c));
    return d;
}
__device__ __forceinline__ void f2_unpack(unsigned long long v, float& lo, float& hi) {
    asm("mov.b64 {%0, %1}, %2;" : "=f"(lo), "=f"(hi) : "l"(v));
}
__device__ __forceinline__ unsigned long long ld_rlx64(const unsigned long long* p) {
    unsigned long long v;
    asm volatile("ld.relaxed.gpu.global.b64 %0, [%1];" : "=l"(v) : "l"(p) : "memory");
    return v;
}
__device__ __forceinline__ void st_rlx64(unsigned long long* p, unsigned long long v) {
    asm volatile("st.relaxed.gpu.global.b64 [%0], %1;" :: "l"(p), "l"(v) : "memory");
}
__device__ __forceinline__ uint32_t smem_u32(const void* p) {
    uint32_t a;
    asm("{ .reg .u64 t; cvta.to.shared.u64 t, %1; cvt.u32.u64 %0, t; }"
        : "=r"(a) : "l"(p));
    return a;
}

// ---- mma.sync / ldmatrix / cp.async helpers (sm_80+ PTX, target-safe) ----
__device__ __forceinline__ void ldsm4(uint32_t addr, uint32_t& r0, uint32_t& r1,
                                      uint32_t& r2, uint32_t& r3) {
    asm volatile("ldmatrix.sync.aligned.m8n8.x4.shared.b16 {%0,%1,%2,%3}, [%4];"
                 : "=r"(r0), "=r"(r1), "=r"(r2), "=r"(r3) : "r"(addr));
}
__device__ __forceinline__ void mma16816(float* c, uint32_t a0, uint32_t a1,
                                         uint32_t a2, uint32_t a3,
                                         uint32_t b0, uint32_t b1) {
    asm volatile(
        "mma.sync.aligned.m16n8k16.row.col.f32.bf16.bf16.f32 "
        "{%0,%1,%2,%3}, {%4,%5,%6,%7}, {%8,%9}, {%0,%1,%2,%3};"
        : "+f"(c[0]), "+f"(c[1]), "+f"(c[2]), "+f"(c[3])
        : "r"(a0), "r"(a1), "r"(a2), "r"(a3), "r"(b0), "r"(b1));
}
__device__ __forceinline__ void cpa16(uint32_t s, const void* g) {
    asm volatile("cp.async.cg.shared.global [%0], [%1], 16;" :: "r"(s), "l"(g));
}
#define CPA_COMMIT() asm volatile("cp.async.commit_group;" ::: "memory")
#define CPA_WAIT0()  asm volatile("cp.async.wait_group 0;" ::: "memory")

// =====================================================================
// Kernel A: gi = emb[t] @ w_ih^T + b_ih. Block(0,0) zeroes h tags.
// =====================================================================
__global__ void __launch_bounds__(256)
embed_gi_kernel(const int* __restrict__ t,
                const float* __restrict__ emb,
                const float* __restrict__ w_ih,
                const float* __restrict__ b_ih) {
    int tid = threadIdx.x;
    if (blockIdx.x == 0 && blockIdx.y == 0) {
        unsigned long long* p = &g_htag[0][0][0];
        for (int i = tid; i < 2 * NBATCH * HDIM; i += 256) p[i] = 0ull;
    }

    __shared__ float As[32][64];
    __shared__ float Bs[32][64];
    __shared__ int   tok[64];

    int m0 = blockIdx.y * 64;
    int n0 = blockIdx.x * 64;

    if (tid < 64) tok[tid] = t[m0 + tid];
    __syncthreads();

    int tm = tid >> 4;
    int tn = tid & 15;
    float c[4][4];
#pragma unroll
    for (int i = 0; i < 4; i++)
#pragma unroll
        for (int j = 0; j < 4; j++) c[i][j] = 0.f;

    for (int kc = 0; kc < EDIM; kc += 32) {
#pragma unroll
        for (int r = 0; r < 2; r++) {
            int f   = tid + 256 * r;
            int row = f >> 3;
            int c4  = f & 7;
            float4 av = *reinterpret_cast<const float4*>(
                &emb[(size_t)tok[row] * EDIM + kc + c4 * 4]);
            As[c4 * 4 + 0][row] = av.x; As[c4 * 4 + 1][row] = av.y;
            As[c4 * 4 + 2][row] = av.z; As[c4 * 4 + 3][row] = av.w;
            float4 bv = *reinterpret_cast<const float4*>(
                &w_ih[(size_t)(n0 + row) * EDIM + kc + c4 * 4]);
            Bs[c4 * 4 + 0][row] = bv.x; Bs[c4 * 4 + 1][row] = bv.y;
            Bs[c4 * 4 + 2][row] = bv.z; Bs[c4 * 4 + 3][row] = bv.w;
        }
        __syncthreads();
#pragma unroll
        for (int k = 0; k < 32; k++) {
            float a[4], b[4];
#pragma unroll
            for (int i = 0; i < 4; i++) a[i] = As[k][tm * 4 + i];
#pragma unroll
            for (int j = 0; j < 4; j++) b[j] = Bs[k][tn * 4 + j];
#pragma unroll
            for (int i = 0; i < 4; i++)
#pragma unroll
                for (int j = 0; j < 4; j++) c[i][j] += a[i] * b[j];
        }
        __syncthreads();
    }

#pragma unroll
    for (int i = 0; i < 4; i++) {
        int m = m0 + tm * 4 + i;
#pragma unroll
        for (int j = 0; j < 4; j++) {
            int n = n0 + tn * 4 + j;
            g_gi[(size_t)m * G3 + n] = c[i][j] + b_ih[n];
        }
    }
}

// =====================================================================
// Split kernels: fp32 -> bf16 (hi, lo) with layout
//   A'[k]=a_hi, A'[256+k]=a_lo, A'[512+k]=a_hi
//   B'[k]=b_hi, B'[256+k]=b_hi, B'[512+k]=b_lo
// so A'.B' = hi*hi + lo*hi + hi*lo  (missing only lo*lo ~ 2^-18)
// =====================================================================
__global__ void __launch_bounds__(256)
split_w_kernel(const float* __restrict__ w_out) {
    int idx = blockIdx.x * 256 + threadIdx.x;    // over 32000*64
    int v  = idx >> 6;
    int k4 = (idx & 63) * 4;
    float4 w = *reinterpret_cast<const float4*>(&w_out[(size_t)v * HDIM + k4]);
    __nv_bfloat16* row = &g_B2[(size_t)v * KP];
    float ws[4] = {w.x, w.y, w.z, w.w};
#pragma unroll
    for (int j = 0; j < 4; j++) {
        __nv_bfloat16 hi = __float2bfloat16_rn(ws[j]);
        __nv_bfloat16 lo = __float2bfloat16_rn(ws[j] - __bfloat162float(hi));
        row[k4 + j]       = hi;
        row[256 + k4 + j] = hi;
        row[512 + k4 + j] = lo;
    }
}

__global__ void __launch_bounds__(256)
split_h_kernel() {
    int idx = blockIdx.x * 256 + threadIdx.x;    // over 4096*64
    int m  = idx >> 6;
    int k4 = (idx & 63) * 4;
    float4 h = *reinterpret_cast<const float4*>(&g_hidden[(size_t)m * HDIM + k4]);
    __nv_bfloat16* row = &g_A2[(size_t)m * KP];
    float hs[4] = {h.x, h.y, h.z, h.w};
#pragma unroll
    for (int j = 0; j < 4; j++) {
        __nv_bfloat16 hi = __float2bfloat16_rn(hs[j]);
        __nv_bfloat16 lo = __float2bfloat16_rn(hs[j] - __bfloat162float(hi));
        row[k4 + j]       = hi;
        row[256 + k4 + j] = lo;
        row[512 + k4 + j] = hi;
    }
}

// =====================================================================
// Kernel B: GRU recurrence (round-6 verified version, unchanged).
// =====================================================================
#define GRU_NBLK 64
#define GRU_TPB  384

__global__ void __launch_bounds__(GRU_TPB, 1)
gru_kernel(const float* __restrict__ h0,
           const float* __restrict__ w_hh,
           const float* __restrict__ b_hh) {
    int tid = threadIdx.x;
    int blk = blockIdx.x;
    int b   = blk >> 3;
    int g   = blk & 7;

    int lr = tid >> 2;
    int ks = tid & 3;
    int gate = lr >> 5;
    int u    = lr & 31;
    int grow = gate * HDIM + g * 32 + u;
    int lane = tid & 31;

    unsigned long long w2[32];
#pragma unroll
    for (int j = 0; j < 16; j++) {
        float4 wv = *reinterpret_cast<const float4*>(
            &w_hh[(size_t)grow * HDIM + (j * 4 + ks) * 4]);
        w2[2 * j]     = f2_pack(wv.x, wv.y);
        w2[2 * j + 1] = f2_pack(wv.z, wv.w);
    }
    float bias = b_hh[grow];

    __shared__ __align__(16) float h_s[HDIM];
    __shared__ float gh_s[96];

    float hold = 0.f;
    if (tid < 32) {
        hold = h0[g * 32 + lane];
        unsigned long long word =
            (1ull << 32) | (unsigned long long)__float_as_uint(hold);
        st_rlx64(&g_htag[0][b][g * 32 + lane], word);
    }

    for (int s = 0; s < SEQ; s++) {
        int p = s & 1;
        unsigned want = (unsigned)(s + 1);

        float gir = 0.f, giz = 0.f, gin = 0.f;
        if (tid < 32) {
            size_t m = (size_t)b * SEQ + s;
            const float* gm = &g_gi[m * G3 + g * 32 + lane];
            gir = __ldg(gm);
            giz = __ldg(gm + HDIM);
            gin = __ldg(gm + 2 * HDIM);
        }

        if (tid < HDIM) {
            const unsigned long long* wp = &g_htag[p][b][tid];
            unsigned long long v = ld_rlx64(wp);
            while ((unsigned)(v >> 32) != want) v = ld_rlx64(wp);
            h_s[tid] = __uint_as_float((unsigned)v);
        }
        __syncthreads();

        unsigned long long acc0 = 0ull, acc1 = 0ull;
        const ulonglong2* hp = reinterpret_cast<const ulonglong2*>(h_s);
#pragma unroll
        for (int j = 0; j < 16; j++) {
            ulonglong2 hv = hp[j * 4 + ks];
            acc0 = f2_fma(w2[2 * j],     hv.x, acc0);
            acc1 = f2_fma(w2[2 * j + 1], hv.y, acc1);
        }
        float a0, a1, a2, a3;
        f2_unpack(acc0, a0, a1);
        f2_unpack(acc1, a2, a3);
        float acc = (a0 + a1) + (a2 + a3);
        acc += __shfl_xor_sync(0xffffffffu, acc, 1);
        acc += __shfl_xor_sync(0xffffffffu, acc, 2);
        if (ks == 0) gh_s[lr] = acc + bias;
        __syncthreads();

        if (tid < 32) {
            float hrv = gh_s[lane];
            float hzv = gh_s[32 + lane];
            float hnv = gh_s[64 + lane];
            float r = 1.f / (1.f + __expf(-(gir + hrv)));
            float z = 1.f / (1.f + __expf(-(giz + hzv)));
            float n = tanhf(gin + r * hnv);
            float hnew = (1.f - z) * n + z * hold;
            hold = hnew;
            g_hidden[((size_t)b * SEQ + s) * HDIM + g * 32 + lane] = hnew;
            unsigned long long word =
                ((unsigned long long)(unsigned)(s + 2) << 32) |
                (unsigned long long)__float_as_uint(hnew);
            st_rlx64(&g_htag[p ^ 1][b][g * 32 + lane], word);
        }
    }
}

// =====================================================================
// Kernel C: out = A' @ B'^T + b_out via mma.sync m16n8k16 bf16 (HMMA).
// CTA tile 128x128, 8 warps (2x4) of 64x32. K'=768 in 12 chunks of 64,
// cp.async double-buffered smem (rows padded to 144B), non-trans
// ldmatrix for both A ([m][k] row-major) and B ([n][k] = col-major B).
// =====================================================================
#define KCH      64
#define NCHUNKS  12
#define ROWB     144                      // (64+8) bf16 row stride in bytes
#define ABUF_SZ  (128 * ROWB)             // 18432 B
#define SAOFF(buf) ((buf) * ABUF_SZ)
#define SBOFF(buf) (2 * ABUF_SZ + (buf) * ABUF_SZ)
#define GEMM_SMEM (4 * ABUF_SZ)           // 73728 B

__global__ void __launch_bounds__(256)
out_gemm_mma(const float* __restrict__ b_out, float* __restrict__ out) {
    extern __shared__ char smem[];
    uint32_t sb = smem_u32(smem);
    int tid = threadIdx.x;
    int wid = tid >> 5;
    int lane = tid & 31;
    int warp_m = wid >> 2;        // 0..1
    int warp_n = wid & 3;         // 0..3
    int m0 = blockIdx.y * 128;
    int n0 = blockIdx.x * 128;

    int g = lane >> 2;            // 0..7
    int t = lane & 3;             // 0..3

    // cp.async issue of one K-chunk into buffer `buf`
    auto issue = [&](int c, int buf) {
#pragma unroll
        for (int i = 0; i < 4; i++) {
            int f = tid + 256 * i;       // 0..1023
            int row = f >> 3;            // 0..127
            int q = f & 7;               // 0..7 (16B units)
            cpa16(sb + SAOFF(buf) + row * ROWB + q * 16,
                  &g_A2[(size_t)(m0 + row) * KP + c * KCH + q * 8]);
            cpa16(sb + SBOFF(buf) + row * ROWB + q * 16,
                  &g_B2[(size_t)(n0 + row) * KP + c * KCH + q * 8]);
        }
    };

    // lane-invariant ldmatrix address pieces
    //   A: row = warp_m*64 + mt*16 + (lane&15), col byte = ((lane>>4)&1)*16
    //   B: row = warp_n*32 + p*16 + (lane&7) + ((lane>>4)&1)*8,
    //      col byte = ((lane>>3)&1)*16
    uint32_t a_lane = (uint32_t)((warp_m * 64 + (lane & 15)) * ROWB +
                                 ((lane >> 4) & 1) * 16);
    uint32_t b_lane = (uint32_t)((warp_n * 32 + (lane & 7) +
                                  ((lane >> 4) & 1) * 8) * ROWB +
                                 ((lane >> 3) & 1) * 16);

    float acc[4][4][4];
#pragma unroll
    for (int i = 0; i < 4; i++)
#pragma unroll
        for (int j = 0; j < 4; j++)
#pragma unroll
            for (int e = 0; e < 4; e++) acc[i][j][e] = 0.f;

    issue(0, 0);
    CPA_COMMIT();

    for (int c = 0; c < NCHUNKS; c++) {
        int buf = c & 1;
        CPA_WAIT0();
        __syncthreads();
        if (c + 1 < NCHUNKS) {
            issue(c + 1, buf ^ 1);
            CPA_COMMIT();
        }
        uint32_t abase = sb + SAOFF(buf) + a_lane;
        uint32_t bbase = sb + SBOFF(buf) + b_lane;
#pragma unroll
        for (int ks = 0; ks < 4; ks++) {
            uint32_t kb = (uint32_t)(ks * 32);   // 16 bf16 = 32 bytes
            uint32_t a[4][4];
#pragma unroll
            for (int mt = 0; mt < 4; mt++)
                ldsm4(abase + mt * 16 * ROWB + kb,
                      a[mt][0], a[mt][1], a[mt][2], a[mt][3]);
            uint32_t b[4][2];
#pragma unroll
            for (int p = 0; p < 2; p++) {
                uint32_t r0, r1, r2, r3;
                ldsm4(bbase + p * 16 * ROWB + kb, r0, r1, r2, r3);
                b[2 * p][0] = r0; b[2 * p][1] = r1;
                b[2 * p + 1][0] = r2; b[2 * p + 1][1] = r3;
            }
#pragma unroll
            for (int mt = 0; mt < 4; mt++)
#pragma unroll
                for (int nt = 0; nt < 4; nt++)
                    mma16816(acc[mt][nt], a[mt][0], a[mt][1], a[mt][2],
                             a[mt][3], b[nt][0], b[nt][1]);
        }
    }

    // epilogue: c0,c1 -> (row g, cols 2t,2t+1); c2,c3 -> (row g+8)
#pragma unroll
    for (int mt = 0; mt < 4; mt++) {
        int r0 = m0 + warp_m * 64 + mt * 16 + g;
#pragma unroll
        for (int nt = 0; nt < 4; nt++) {
            int col = n0 + warp_n * 32 + nt * 8 + 2 * t;
            float2 bi = *reinterpret_cast<const float2*>(&b_out[col]);
            float2 o0 = {acc[mt][nt][0] + bi.x, acc[mt][nt][1] + bi.y};
            float2 o1 = {acc[mt][nt][2] + bi.x, acc[mt][nt][3] + bi.y};
            *reinterpret_cast<float2*>(&out[(size_t)r0 * VOCAB + col]) = o0;
            *reinterpret_cast<float2*>(&out[(size_t)(r0 + 8) * VOCAB + col]) = o1;
        }
    }
}

// =====================================================================
// launch
// =====================================================================
extern "C" void kernel_launch(void* const* d_in, const int* in_sizes, int n_in,
                              void* d_out, int out_size) {
    const int*   t     = (const int*)d_in[0];
    const float* emb   = (const float*)d_in[1];
    const float* h0    = (const float*)d_in[2];
    const float* w_ih  = (const float*)d_in[3];
    const float* w_hh  = (const float*)d_in[4];
    const float* b_ih  = (const float*)d_in[5];
    const float* b_hh  = (const float*)d_in[6];
    const float* w_out = (const float*)d_in[7];
    const float* b_out = (const float*)d_in[8];
    float* out = (float*)d_out;

    cudaFuncSetAttribute(out_gemm_mma,
                         cudaFuncAttributeMaxDynamicSharedMemorySize,
                         GEMM_SMEM);

    embed_gi_kernel<<<dim3(G3 / 64, MTOT / 64), 256>>>(t, emb, w_ih, b_ih);
    split_w_kernel<<<VOCAB * 64 / 256, 256>>>(w_out);
    gru_kernel<<<GRU_NBLK, GRU_TPB>>>(h0, w_hh, b_hh);
    split_h_kernel<<<MTOT * 64 / 256, 256>>>();
    out_gemm_mma<<<dim3(VOCAB / 128, MTOT / 128), 256, GEMM_SMEM>>>(b_out, out);
}

// round 9
// speedup vs baseline: 2.6388x; 1.1142x over previous
#include <cuda_runtime.h>
#include <cuda_bf16.h>
#include <cstdint>

#define VOCAB 32000
#define EDIM  128
#define HDIM  256
#define NBATCH 8
#define SEQ   512
#define MTOT  (NBATCH * SEQ)   // 4096
#define G3    (3 * HDIM)       // 768
#define KP    768              // split K' = 3 * 256

// ---- scratch (static device globals; no allocation) ----
__device__ float g_gi[MTOT * G3];
__device__ __nv_bfloat16 g_A2[(size_t)MTOT * KP];    // [4096][768]
__device__ __nv_bfloat16 g_B2[(size_t)VOCAB * KP];   // [32000][768]

// ---- packed f32x2 helpers ----
__device__ __forceinline__ unsigned long long f2_pack(float x, float y) {
    unsigned long long r;
    asm("mov.b64 %0, {%1, %2};" : "=l"(r) : "f"(x), "f"(y));
    return r;
}
__device__ __forceinline__ unsigned long long f2_fma(unsigned long long a,
                                                     unsigned long long b,
                                                     unsigned long long c) {
    unsigned long long d;
    asm("fma.rn.f32x2 %0, %1, %2, %3;" : "=l"(d) : "l"(a), "l"(b), "l"(c));
    return d;
}
__device__ __forceinline__ void f2_unpack(unsigned long long v, float& lo, float& hi) {
    asm("mov.b64 {%0, %1}, %2;" : "=f"(lo), "=f"(hi) : "l"(v));
}
__device__ __forceinline__ uint32_t smem_u32(const void* p) {
    uint32_t a;
    asm("{ .reg .u64 t; cvta.to.shared.u64 t, %1; cvt.u32.u64 %0, t; }"
        : "=r"(a) : "l"(p));
    return a;
}

// ---- cluster / DSMEM helpers (sm_90 baseline PTX, no 'a' gating) ----
__device__ __forceinline__ uint32_t mapa_u32(uint32_t saddr, uint32_t rank) {
    uint32_t r;
    asm("mapa.shared::cluster.u32 %0, %1, %2;" : "=r"(r) : "r"(saddr), "r"(rank));
    return r;
}
__device__ __forceinline__ void st_clu64(uint32_t addr, unsigned long long v) {
    asm volatile("st.relaxed.cluster.shared::cluster.b64 [%0], %1;"
                 :: "r"(addr), "l"(v) : "memory");
}
__device__ __forceinline__ unsigned long long ld_clu64(uint32_t addr) {
    unsigned long long v;
    asm volatile("ld.relaxed.cluster.shared::cluster.b64 %0, [%1];"
                 : "=l"(v) : "r"(addr) : "memory");
    return v;
}
#define CLUSTER_BAR() do {                                          \
    asm volatile("barrier.cluster.arrive.aligned;" ::: "memory");   \
    asm volatile("barrier.cluster.wait.aligned;" ::: "memory");     \
} while (0)

// ---- mma.sync / ldmatrix / cp.async helpers (sm_80+ PTX, target-safe) ----
__device__ __forceinline__ void ldsm4(uint32_t addr, uint32_t& r0, uint32_t& r1,
                                      uint32_t& r2, uint32_t& r3) {
    asm volatile("ldmatrix.sync.aligned.m8n8.x4.shared.b16 {%0,%1,%2,%3}, [%4];"
                 : "=r"(r0), "=r"(r1), "=r"(r2), "=r"(r3) : "r"(addr));
}
__device__ __forceinline__ void mma16816(float* c, uint32_t a0, uint32_t a1,
                                         uint32_t a2, uint32_t a3,
                                         uint32_t b0, uint32_t b1) {
    asm volatile(
        "mma.sync.aligned.m16n8k16.row.col.f32.bf16.bf16.f32 "
        "{%0,%1,%2,%3}, {%4,%5,%6,%7}, {%8,%9}, {%0,%1,%2,%3};"
        : "+f"(c[0]), "+f"(c[1]), "+f"(c[2]), "+f"(c[3])
        : "r"(a0), "r"(a1), "r"(a2), "r"(a3), "r"(b0), "r"(b1));
}
__device__ __forceinline__ void cpa16(uint32_t s, const void* g) {
    asm volatile("cp.async.cg.shared.global [%0], [%1], 16;" :: "r"(s), "l"(g));
}
#define CPA_COMMIT() asm volatile("cp.async.commit_group;" ::: "memory")
#define CPA_WAIT0()  asm volatile("cp.async.wait_group 0;" ::: "memory")

// =====================================================================
// Kernel A: gi = emb[t] @ w_ih^T + b_ih (verified round-4/6 version).
// =====================================================================
__global__ void __launch_bounds__(256)
embed_gi_kernel(const int* __restrict__ t,
                const float* __restrict__ emb,
                const float* __restrict__ w_ih,
                const float* __restrict__ b_ih) {
    int tid = threadIdx.x;

    __shared__ float As[32][64];
    __shared__ float Bs[32][64];
    __shared__ int   tok[64];

    int m0 = blockIdx.y * 64;
    int n0 = blockIdx.x * 64;

    if (tid < 64) tok[tid] = t[m0 + tid];
    __syncthreads();

    int tm = tid >> 4;
    int tn = tid & 15;
    float c[4][4];
#pragma unroll
    for (int i = 0; i < 4; i++)
#pragma unroll
        for (int j = 0; j < 4; j++) c[i][j] = 0.f;

    for (int kc = 0; kc < EDIM; kc += 32) {
#pragma unroll
        for (int r = 0; r < 2; r++) {
            int f   = tid + 256 * r;
            int row = f >> 3;
            int c4  = f & 7;
            float4 av = *reinterpret_cast<const float4*>(
                &emb[(size_t)tok[row] * EDIM + kc + c4 * 4]);
            As[c4 * 4 + 0][row] = av.x; As[c4 * 4 + 1][row] = av.y;
            As[c4 * 4 + 2][row] = av.z; As[c4 * 4 + 3][row] = av.w;
            float4 bv = *reinterpret_cast<const float4*>(
                &w_ih[(size_t)(n0 + row) * EDIM + kc + c4 * 4]);
            Bs[c4 * 4 + 0][row] = bv.x; Bs[c4 * 4 + 1][row] = bv.y;
            Bs[c4 * 4 + 2][row] = bv.z; Bs[c4 * 4 + 3][row] = bv.w;
        }
        __syncthreads();
#pragma unroll
        for (int k = 0; k < 32; k++) {
            float a[4], b[4];
#pragma unroll
            for (int i = 0; i < 4; i++) a[i] = As[k][tm * 4 + i];
#pragma unroll
            for (int j = 0; j < 4; j++) b[j] = Bs[k][tn * 4 + j];
#pragma unroll
            for (int i = 0; i < 4; i++)
#pragma unroll
                for (int j = 0; j < 4; j++) c[i][j] += a[i] * b[j];
        }
        __syncthreads();
    }

#pragma unroll
    for (int i = 0; i < 4; i++) {
        int m = m0 + tm * 4 + i;
#pragma unroll
        for (int j = 0; j < 4; j++) {
            int n = n0 + tn * 4 + j;
            g_gi[(size_t)m * G3 + n] = c[i][j] + b_ih[n];
        }
    }
}

// =====================================================================
// split_w: w_out fp32 -> B2 bf16 [b_hi | b_hi | b_lo]  (K'=768)
// =====================================================================
__global__ void __launch_bounds__(256)
split_w_kernel(const float* __restrict__ w_out) {
    int idx = blockIdx.x * 256 + threadIdx.x;    // over 32000*64
    int v  = idx >> 6;
    int k4 = (idx & 63) * 4;
    float4 w = *reinterpret_cast<const float4*>(&w_out[(size_t)v * HDIM + k4]);
    __nv_bfloat16* row = &g_B2[(size_t)v * KP];
    float ws[4] = {w.x, w.y, w.z, w.w};
#pragma unroll
    for (int j = 0; j < 4; j++) {
        __nv_bfloat16 hi = __float2bfloat16_rn(ws[j]);
        __nv_bfloat16 lo = __float2bfloat16_rn(ws[j] - __bfloat162float(hi));
        row[k4 + j]       = hi;
        row[256 + k4 + j] = hi;
        row[512 + k4 + j] = lo;
    }
}

// =====================================================================
// Kernel B: GRU recurrence with DSMEM tag exchange.
// Cluster of 8 CTAs = one batch; rank = unit group g (32 units).
// Same tagged-word protocol as verified L2 version, but publishes go to
// every cluster CTA's smem (mapa + st.relaxed.cluster) and polls read
// local smem. Combine warp fuses the bf16 hi/lo split into g_A2
// (A layout: [a_hi | a_lo | a_hi]).
// =====================================================================
#define GRU_NBLK 64
#define GRU_TPB  384

__global__ void __launch_bounds__(GRU_TPB, 1) __cluster_dims__(8, 1, 1)
gru_kernel(const float* __restrict__ h0,
           const float* __restrict__ w_hh,
           const float* __restrict__ b_hh) {
    __shared__ __align__(16) unsigned long long htag[2][HDIM];
    __shared__ __align__(16) float h_s[HDIM];
    __shared__ float gh_s[96];

    int tid = threadIdx.x;
    int blk = blockIdx.x;
    int b   = blk >> 3;      // batch = cluster id
    int g   = blk & 7;       // unit group = cluster rank

    int lr = tid >> 2;       // local gate row 0..95
    int ks = tid & 3;        // k-slice 0..3
    int gate = lr >> 5;
    int u    = lr & 31;
    int grow = gate * HDIM + g * 32 + u;
    int lane = tid & 31;

    // w_hh slice in registers, packed for f32x2
    unsigned long long w2[32];
#pragma unroll
    for (int j = 0; j < 16; j++) {
        float4 wv = *reinterpret_cast<const float4*>(
            &w_hh[(size_t)grow * HDIM + (j * 4 + ks) * 4]);
        w2[2 * j]     = f2_pack(wv.x, wv.y);
        w2[2 * j + 1] = f2_pack(wv.z, wv.w);
    }
    float bias = b_hh[grow];

    // zero tag buffers (fresh smem each launch/replay), then cluster-sync
    for (int i = tid; i < 2 * HDIM; i += GRU_TPB) htag[0][i & 255 ? i & 255 : 0] = 0ull;
    // (simple flat zeroing; rewrite plainly:)
    {
        unsigned long long* ft = &htag[0][0];
        for (int i = tid; i < 2 * HDIM; i += GRU_TPB) ft[i] = 0ull;
    }
    __syncthreads();
    CLUSTER_BAR();

    // precompute DSMEM addresses
    uint32_t poll_addr[2];
    {
        uint32_t a0 = smem_u32(&htag[0][tid < HDIM ? tid : 0]);
        uint32_t a1 = smem_u32(&htag[1][tid < HDIM ? tid : 0]);
        poll_addr[0] = mapa_u32(a0, (uint32_t)g);   // own-rank mapping
        poll_addr[1] = mapa_u32(a1, (uint32_t)g);
    }
    uint32_t pub_addr[2][8];
    {
        uint32_t a0 = smem_u32(&htag[0][g * 32 + lane]);
        uint32_t a1 = smem_u32(&htag[1][g * 32 + lane]);
#pragma unroll
        for (int r = 0; r < 8; r++) {
            pub_addr[0][r] = mapa_u32(a0, (uint32_t)r);
            pub_addr[1][r] = mapa_u32(a1, (uint32_t)r);
        }
    }

    // combine warp publishes h0 (tag 1) into buffer 0 of all 8 CTAs
    float hold = 0.f;
    if (tid < 32) {
        hold = h0[g * 32 + lane];
        unsigned long long word =
            (1ull << 32) | (unsigned long long)__float_as_uint(hold);
#pragma unroll
        for (int r = 0; r < 8; r++) st_clu64(pub_addr[0][r], word);
    }

    for (int s = 0; s < SEQ; s++) {
        int p = s & 1;
        unsigned want = (unsigned)(s + 1);

        // prefetch input-side gate preacts (combine warp)
        float gir = 0.f, giz = 0.f, gin = 0.f;
        if (tid < 32) {
            size_t m = (size_t)b * SEQ + s;
            const float* gm = &g_gi[m * G3 + g * 32 + lane];
            gir = __ldg(gm);
            giz = __ldg(gm + HDIM);
            gin = __ldg(gm + 2 * HDIM);
        }

        // poll local smem tag words (written by cluster peers via DSMEM)
        if (tid < HDIM) {
            unsigned long long v = ld_clu64(poll_addr[p]);
            while ((unsigned)(v >> 32) != want) v = ld_clu64(poll_addr[p]);
            h_s[tid] = __uint_as_float((unsigned)v);
        }
        __syncthreads();

        // partial dot over 64-element k-slice (packed f32x2)
        unsigned long long acc0 = 0ull, acc1 = 0ull;
        const ulonglong2* hp = reinterpret_cast<const ulonglong2*>(h_s);
#pragma unroll
        for (int j = 0; j < 16; j++) {
            ulonglong2 hv = hp[j * 4 + ks];
            acc0 = f2_fma(w2[2 * j],     hv.x, acc0);
            acc1 = f2_fma(w2[2 * j + 1], hv.y, acc1);
        }
        float a0, a1, a2, a3;
        f2_unpack(acc0, a0, a1);
        f2_unpack(acc1, a2, a3);
        float acc = (a0 + a1) + (a2 + a3);
        acc += __shfl_xor_sync(0xffffffffu, acc, 1);
        acc += __shfl_xor_sync(0xffffffffu, acc, 2);
        if (ks == 0) gh_s[lr] = acc + bias;
        __syncthreads();

        // combine gates; publish first (critical path), then write A2
        if (tid < 32) {
            float hrv = gh_s[lane];
            float hzv = gh_s[32 + lane];
            float hnv = gh_s[64 + lane];
            float r = 1.f / (1.f + __expf(-(gir + hrv)));
            float z = 1.f / (1.f + __expf(-(giz + hzv)));
            float n = tanhf(gin + r * hnv);
            float hnew = (1.f - z) * n + z * hold;
            hold = hnew;
            if (s + 1 < SEQ) {   // never write a possibly-exited CTA's smem
                unsigned long long word =
                    ((unsigned long long)(unsigned)(s + 2) << 32) |
                    (unsigned long long)__float_as_uint(hnew);
#pragma unroll
                for (int r8 = 0; r8 < 8; r8++)
                    st_clu64(pub_addr[p ^ 1][r8], word);
            }
            // fused split_h: A' row = [a_hi | a_lo | a_hi]
            __nv_bfloat16 hi = __float2bfloat16_rn(hnew);
            __nv_bfloat16 lo =
                __float2bfloat16_rn(hnew - __bfloat162float(hi));
            __nv_bfloat16* row =
                &g_A2[((size_t)b * SEQ + s) * KP + g * 32 + lane];
            row[0]   = hi;
            row[256] = lo;
            row[512] = hi;
        }
        // protocol invariant (verified R6/R8): no block barrier needed.
    }
}

// =====================================================================
// Kernel C: out = A' @ B'^T + b_out via mma.sync m16n8k16 bf16 (HMMA).
// (round-8 verified version, unchanged)
// =====================================================================
#define KCH      64
#define NCHUNKS  12
#define ROWB     144                      // (64+8) bf16 row stride in bytes
#define ABUF_SZ  (128 * ROWB)             // 18432 B
#define SAOFF(buf) ((buf) * ABUF_SZ)
#define SBOFF(buf) (2 * ABUF_SZ + (buf) * ABUF_SZ)
#define GEMM_SMEM (4 * ABUF_SZ)           // 73728 B

__global__ void __launch_bounds__(256)
out_gemm_mma(const float* __restrict__ b_out, float* __restrict__ out) {
    extern __shared__ char smem[];
    uint32_t sb = smem_u32(smem);
    int tid = threadIdx.x;
    int wid = tid >> 5;
    int lane = tid & 31;
    int warp_m = wid >> 2;        // 0..1
    int warp_n = wid & 3;         // 0..3
    int m0 = blockIdx.y * 128;
    int n0 = blockIdx.x * 128;

    int g = lane >> 2;            // 0..7
    int t = lane & 3;             // 0..3

    auto issue = [&](int c, int buf) {
#pragma unroll
        for (int i = 0; i < 4; i++) {
            int f = tid + 256 * i;
            int row = f >> 3;
            int q = f & 7;
            cpa16(sb + SAOFF(buf) + row * ROWB + q * 16,
                  &g_A2[(size_t)(m0 + row) * KP + c * KCH + q * 8]);
            cpa16(sb + SBOFF(buf) + row * ROWB + q * 16,
                  &g_B2[(size_t)(n0 + row) * KP + c * KCH + q * 8]);
        }
    };

    uint32_t a_lane = (uint32_t)((warp_m * 64 + (lane & 15)) * ROWB +
                                 ((lane >> 4) & 1) * 16);
    uint32_t b_lane = (uint32_t)((warp_n * 32 + (lane & 7) +
                                  ((lane >> 4) & 1) * 8) * ROWB +
                                 ((lane >> 3) & 1) * 16);

    float acc[4][4][4];
#pragma unroll
    for (int i = 0; i < 4; i++)
#pragma unroll
        for (int j = 0; j < 4; j++)
#pragma unroll
            for (int e = 0; e < 4; e++) acc[i][j][e] = 0.f;

    issue(0, 0);
    CPA_COMMIT();

    for (int c = 0; c < NCHUNKS; c++) {
        int buf = c & 1;
        CPA_WAIT0();
        __syncthreads();
        if (c + 1 < NCHUNKS) {
            issue(c + 1, buf ^ 1);
            CPA_COMMIT();
        }
        uint32_t abase = sb + SAOFF(buf) + a_lane;
        uint32_t bbase = sb + SBOFF(buf) + b_lane;
#pragma unroll
        for (int ks = 0; ks < 4; ks++) {
            uint32_t kb = (uint32_t)(ks * 32);
            uint32_t a[4][4];
#pragma unroll
            for (int mt = 0; mt < 4; mt++)
                ldsm4(abase + mt * 16 * ROWB + kb,
                      a[mt][0], a[mt][1], a[mt][2], a[mt][3]);
            uint32_t bq[4][2];
#pragma unroll
            for (int p = 0; p < 2; p++) {
                uint32_t r0, r1, r2, r3;
                ldsm4(bbase + p * 16 * ROWB + kb, r0, r1, r2, r3);
                bq[2 * p][0] = r0; bq[2 * p][1] = r1;
                bq[2 * p + 1][0] = r2; bq[2 * p + 1][1] = r3;
            }
#pragma unroll
            for (int mt = 0; mt < 4; mt++)
#pragma unroll
                for (int nt = 0; nt < 4; nt++)
                    mma16816(acc[mt][nt], a[mt][0], a[mt][1], a[mt][2],
                             a[mt][3], bq[nt][0], bq[nt][1]);
        }
    }

#pragma unroll
    for (int mt = 0; mt < 4; mt++) {
        int r0 = m0 + warp_m * 64 + mt * 16 + g;
#pragma unroll
        for (int nt = 0; nt < 4; nt++) {
            int col = n0 + warp_n * 32 + nt * 8 + 2 * t;
            float2 bi = *reinterpret_cast<const float2*>(&b_out[col]);
            float2 o0 = {acc[mt][nt][0] + bi.x, acc[mt][nt][1] + bi.y};
            float2 o1 = {acc[mt][nt][2] + bi.x, acc[mt][nt][3] + bi.y};
            *reinterpret_cast<float2*>(&out[(size_t)r0 * VOCAB + col]) = o0;
            *reinterpret_cast<float2*>(&out[(size_t)(r0 + 8) * VOCAB + col]) = o1;
        }
    }
}

// =====================================================================
// launch
// =====================================================================
extern "C" void kernel_launch(void* const* d_in, const int* in_sizes, int n_in,
                              void* d_out, int out_size) {
    const int*   t     = (const int*)d_in[0];
    const float* emb   = (const float*)d_in[1];
    const float* h0    = (const float*)d_in[2];
    const float* w_ih  = (const float*)d_in[3];
    const float* w_hh  = (const float*)d_in[4];
    const float* b_ih  = (const float*)d_in[5];
    const float* b_hh  = (const float*)d_in[6];
    const float* w_out = (const float*)d_in[7];
    const float* b_out = (const float*)d_in[8];
    float* out = (float*)d_out;

    cudaFuncSetAttribute(out_gemm_mma,
                         cudaFuncAttributeMaxDynamicSharedMemorySize,
                         GEMM_SMEM);

    embed_gi_kernel<<<dim3(G3 / 64, MTOT / 64), 256>>>(t, emb, w_ih, b_ih);
    split_w_kernel<<<VOCAB * 64 / 256, 256>>>(w_out);
    gru_kernel<<<GRU_NBLK, GRU_TPB>>>(h0, w_hh, b_hh);
    out_gemm_mma<<<dim3(VOCAB / 128, MTOT / 128), 256, GEMM_SMEM>>>(b_out, out);
}

// round 10
// speedup vs baseline: 2.7207x; 1.0311x over previous
#include <cuda_runtime.h>
#include <cuda_bf16.h>
#include <cstdint>

#define VOCAB 32000
#define EDIM  128
#define HDIM  256
#define NBATCH 8
#define SEQ   512
#define MTOT  (NBATCH * SEQ)   // 4096
#define G3    (3 * HDIM)       // 768
#define KP    768              // split K' = 3 * 256

// ---- scratch (static device globals; no allocation) ----
__device__ float g_gi[MTOT * G3];
__device__ __nv_bfloat16 g_A2[(size_t)MTOT * KP];    // [4096][768]
__device__ __nv_bfloat16 g_B2[(size_t)VOCAB * KP];   // [32000][768]

// ---- packed f32x2 helpers ----
__device__ __forceinline__ unsigned long long f2_pack(float x, float y) {
    unsigned long long r;
    asm("mov.b64 %0, {%1, %2};" : "=l"(r) : "f"(x), "f"(y));
    return r;
}
__device__ __forceinline__ unsigned long long f2_fma(unsigned long long a,
                                                     unsigned long long b,
                                                     unsigned long long c) {
    unsigned long long d;
    asm("fma.rn.f32x2 %0, %1, %2, %3;" : "=l"(d) : "l"(a), "l"(b), "l"(c));
    return d;
}
__device__ __forceinline__ void f2_unpack(unsigned long long v, float& lo, float& hi) {
    asm("mov.b64 {%0, %1}, %2;" : "=f"(lo), "=f"(hi) : "l"(v));
}
__device__ __forceinline__ uint32_t smem_u32(const void* p) {
    uint32_t a;
    asm("{ .reg .u64 t; cvta.to.shared.u64 t, %1; cvt.u32.u64 %0, t; }"
        : "=r"(a) : "l"(p));
    return a;
}

// ---- cluster / DSMEM helpers (sm_90 baseline PTX, no 'a' gating) ----
__device__ __forceinline__ uint32_t mapa_u32(uint32_t saddr, uint32_t rank) {
    uint32_t r;
    asm("mapa.shared::cluster.u32 %0, %1, %2;" : "=r"(r) : "r"(saddr), "r"(rank));
    return r;
}
__device__ __forceinline__ void st_clu64(uint32_t addr, unsigned long long v) {
    asm volatile("st.relaxed.cluster.shared::cluster.b64 [%0], %1;"
                 :: "r"(addr), "l"(v) : "memory");
}
__device__ __forceinline__ unsigned long long ld_clu64(uint32_t addr) {
    unsigned long long v;
    asm volatile("ld.relaxed.cluster.shared::cluster.b64 %0, [%1];"
                 : "=l"(v) : "r"(addr) : "memory");
    return v;
}
#define CLUSTER_BAR() do {                                          \
    asm volatile("barrier.cluster.arrive.aligned;" ::: "memory");   \
    asm volatile("barrier.cluster.wait.aligned;" ::: "memory");     \
} while (0)

// ---- mma.sync / ldmatrix / cp.async helpers (sm_80+ PTX, target-safe) ----
__device__ __forceinline__ void ldsm4(uint32_t addr, uint32_t& r0, uint32_t& r1,
                                      uint32_t& r2, uint32_t& r3) {
    asm volatile("ldmatrix.sync.aligned.m8n8.x4.shared.b16 {%0,%1,%2,%3}, [%4];"
                 : "=r"(r0), "=r"(r1), "=r"(r2), "=r"(r3) : "r"(addr));
}
__device__ __forceinline__ void mma16816(float* c, uint32_t a0, uint32_t a1,
                                         uint32_t a2, uint32_t a3,
                                         uint32_t b0, uint32_t b1) {
    asm volatile(
        "mma.sync.aligned.m16n8k16.row.col.f32.bf16.bf16.f32 "
        "{%0,%1,%2,%3}, {%4,%5,%6,%7}, {%8,%9}, {%0,%1,%2,%3};"
        : "+f"(c[0]), "+f"(c[1]), "+f"(c[2]), "+f"(c[3])
        : "r"(a0), "r"(a1), "r"(a2), "r"(a3), "r"(b0), "r"(b1));
}
__device__ __forceinline__ void cpa16(uint32_t s, const void* g) {
    asm volatile("cp.async.cg.shared.global [%0], [%1], 16;" :: "r"(s), "l"(g));
}
#define CPA_COMMIT() asm volatile("cp.async.commit_group;" ::: "memory")
#define CPA_WAIT0()  asm volatile("cp.async.wait_group 0;" ::: "memory")

// =====================================================================
// Kernel A: gi = emb[t] @ w_ih^T + b_ih (verified round-4/6 version).
// =====================================================================
__global__ void __launch_bounds__(256)
embed_gi_kernel(const int* __restrict__ t,
                const float* __restrict__ emb,
                const float* __restrict__ w_ih,
                const float* __restrict__ b_ih) {
    int tid = threadIdx.x;

    __shared__ float As[32][64];
    __shared__ float Bs[32][64];
    __shared__ int   tok[64];

    int m0 = blockIdx.y * 64;
    int n0 = blockIdx.x * 64;

    if (tid < 64) tok[tid] = t[m0 + tid];
    __syncthreads();

    int tm = tid >> 4;
    int tn = tid & 15;
    float c[4][4];
#pragma unroll
    for (int i = 0; i < 4; i++)
#pragma unroll
        for (int j = 0; j < 4; j++) c[i][j] = 0.f;

    for (int kc = 0; kc < EDIM; kc += 32) {
#pragma unroll
        for (int r = 0; r < 2; r++) {
            int f   = tid + 256 * r;
            int row = f >> 3;
            int c4  = f & 7;
            float4 av = *reinterpret_cast<const float4*>(
                &emb[(size_t)tok[row] * EDIM + kc + c4 * 4]);
            As[c4 * 4 + 0][row] = av.x; As[c4 * 4 + 1][row] = av.y;
            As[c4 * 4 + 2][row] = av.z; As[c4 * 4 + 3][row] = av.w;
            float4 bv = *reinterpret_cast<const float4*>(
                &w_ih[(size_t)(n0 + row) * EDIM + kc + c4 * 4]);
            Bs[c4 * 4 + 0][row] = bv.x; Bs[c4 * 4 + 1][row] = bv.y;
            Bs[c4 * 4 + 2][row] = bv.z; Bs[c4 * 4 + 3][row] = bv.w;
        }
        __syncthreads();
#pragma unroll
        for (int k = 0; k < 32; k++) {
            float a[4], b[4];
#pragma unroll
            for (int i = 0; i < 4; i++) a[i] = As[k][tm * 4 + i];
#pragma unroll
            for (int j = 0; j < 4; j++) b[j] = Bs[k][tn * 4 + j];
#pragma unroll
            for (int i = 0; i < 4; i++)
#pragma unroll
                for (int j = 0; j < 4; j++) c[i][j] += a[i] * b[j];
        }
        __syncthreads();
    }

#pragma unroll
    for (int i = 0; i < 4; i++) {
        int m = m0 + tm * 4 + i;
#pragma unroll
        for (int j = 0; j < 4; j++) {
            int n = n0 + tn * 4 + j;
            g_gi[(size_t)m * G3 + n] = c[i][j] + b_ih[n];
        }
    }
}

// =====================================================================
// Kernel B: GRU recurrence with DSMEM tag exchange (verified R9 logic)
// PLUS worker clusters: blocks >= 64 grid-stride the split_w job
// (w_out fp32 -> B2 bf16 [b_hi | b_hi | b_lo]) on otherwise-idle SMs.
// =====================================================================
#define GRU_NBLK 64
#define GRU_TPB  384
#define WRK_NBLK 56
#define TOT_NBLK (GRU_NBLK + WRK_NBLK)   // 120, divisible by 8

__global__ void __launch_bounds__(GRU_TPB, 1) __cluster_dims__(8, 1, 1)
gru_kernel(const float* __restrict__ h0,
           const float* __restrict__ w_hh,
           const float* __restrict__ b_hh,
           const float* __restrict__ w_out) {
    __shared__ __align__(16) unsigned long long htag[2][HDIM];
    __shared__ __align__(16) float h_s[HDIM];
    __shared__ float gh_s[96];

    int tid = threadIdx.x;
    int blk = blockIdx.x;

    // ---- worker clusters: split_w ----
    if (blk >= GRU_NBLK) {
        int base = (blk - GRU_NBLK) * GRU_TPB + tid;
        const int stride = WRK_NBLK * GRU_TPB;
        for (int idx = base; idx < VOCAB * 64; idx += stride) {
            int v  = idx >> 6;
            int k4 = (idx & 63) * 4;
            float4 w = *reinterpret_cast<const float4*>(
                &w_out[(size_t)v * HDIM + k4]);
            __nv_bfloat16* row = &g_B2[(size_t)v * KP];
            float ws[4] = {w.x, w.y, w.z, w.w};
#pragma unroll
            for (int j = 0; j < 4; j++) {
                __nv_bfloat16 hi = __float2bfloat16_rn(ws[j]);
                __nv_bfloat16 lo =
                    __float2bfloat16_rn(ws[j] - __bfloat162float(hi));
                row[k4 + j]       = hi;
                row[256 + k4 + j] = hi;
                row[512 + k4 + j] = lo;
            }
        }
        return;
    }

    // ---- GRU clusters (blocks 0..63), logic identical to verified R9 ----
    int b = blk >> 3;        // batch = cluster id
    int g = blk & 7;         // unit group = cluster rank

    int lr = tid >> 2;       // local gate row 0..95
    int ks = tid & 3;        // k-slice 0..3
    int gate = lr >> 5;
    int u    = lr & 31;
    int grow = gate * HDIM + g * 32 + u;
    int lane = tid & 31;

    unsigned long long w2[32];
#pragma unroll
    for (int j = 0; j < 16; j++) {
        float4 wv = *reinterpret_cast<const float4*>(
            &w_hh[(size_t)grow * HDIM + (j * 4 + ks) * 4]);
        w2[2 * j]     = f2_pack(wv.x, wv.y);
        w2[2 * j + 1] = f2_pack(wv.z, wv.w);
    }
    float bias = b_hh[grow];

    {
        unsigned long long* ft = &htag[0][0];
        for (int i = tid; i < 2 * HDIM; i += GRU_TPB) ft[i] = 0ull;
    }
    __syncthreads();
    CLUSTER_BAR();

    uint32_t poll_addr[2];
    {
        uint32_t a0 = smem_u32(&htag[0][tid < HDIM ? tid : 0]);
        uint32_t a1 = smem_u32(&htag[1][tid < HDIM ? tid : 0]);
        poll_addr[0] = mapa_u32(a0, (uint32_t)g);
        poll_addr[1] = mapa_u32(a1, (uint32_t)g);
    }
    uint32_t pub_addr[2][8];
    {
        uint32_t a0 = smem_u32(&htag[0][g * 32 + lane]);
        uint32_t a1 = smem_u32(&htag[1][g * 32 + lane]);
#pragma unroll
        for (int r = 0; r < 8; r++) {
            pub_addr[0][r] = mapa_u32(a0, (uint32_t)r);
            pub_addr[1][r] = mapa_u32(a1, (uint32_t)r);
        }
    }

    float hold = 0.f;
    if (tid < 32) {
        hold = h0[g * 32 + lane];
        unsigned long long word =
            (1ull << 32) | (unsigned long long)__float_as_uint(hold);
#pragma unroll
        for (int r = 0; r < 8; r++) st_clu64(pub_addr[0][r], word);
    }

    for (int s = 0; s < SEQ; s++) {
        int p = s & 1;
        unsigned want = (unsigned)(s + 1);

        float gir = 0.f, giz = 0.f, gin = 0.f;
        if (tid < 32) {
            size_t m = (size_t)b * SEQ + s;
            const float* gm = &g_gi[m * G3 + g * 32 + lane];
            gir = __ldg(gm);
            giz = __ldg(gm + HDIM);
            gin = __ldg(gm + 2 * HDIM);
        }

        if (tid < HDIM) {
            unsigned long long v = ld_clu64(poll_addr[p]);
            while ((unsigned)(v >> 32) != want) v = ld_clu64(poll_addr[p]);
            h_s[tid] = __uint_as_float((unsigned)v);
        }
        __syncthreads();

        unsigned long long acc0 = 0ull, acc1 = 0ull;
        const ulonglong2* hp = reinterpret_cast<const ulonglong2*>(h_s);
#pragma unroll
        for (int j = 0; j < 16; j++) {
            ulonglong2 hv = hp[j * 4 + ks];
            acc0 = f2_fma(w2[2 * j],     hv.x, acc0);
            acc1 = f2_fma(w2[2 * j + 1], hv.y, acc1);
        }
        float a0, a1, a2, a3;
        f2_unpack(acc0, a0, a1);
        f2_unpack(acc1, a2, a3);
        float acc = (a0 + a1) + (a2 + a3);
        acc += __shfl_xor_sync(0xffffffffu, acc, 1);
        acc += __shfl_xor_sync(0xffffffffu, acc, 2);
        if (ks == 0) gh_s[lr] = acc + bias;
        __syncthreads();

        if (tid < 32) {
            float hrv = gh_s[lane];
            float hzv = gh_s[32 + lane];
            float hnv = gh_s[64 + lane];
            float r = 1.f / (1.f + __expf(-(gir + hrv)));
            float z = 1.f / (1.f + __expf(-(giz + hzv)));
            float n = tanhf(gin + r * hnv);
            float hnew = (1.f - z) * n + z * hold;
            hold = hnew;
            if (s + 1 < SEQ) {
                unsigned long long word =
                    ((unsigned long long)(unsigned)(s + 2) << 32) |
                    (unsigned long long)__float_as_uint(hnew);
#pragma unroll
                for (int r8 = 0; r8 < 8; r8++)
                    st_clu64(pub_addr[p ^ 1][r8], word);
            }
            __nv_bfloat16 hi = __float2bfloat16_rn(hnew);
            __nv_bfloat16 lo =
                __float2bfloat16_rn(hnew - __bfloat162float(hi));
            __nv_bfloat16* row =
                &g_A2[((size_t)b * SEQ + s) * KP + g * 32 + lane];
            row[0]   = hi;
            row[256] = lo;
            row[512] = hi;
        }
    }
}

// =====================================================================
// Kernel C: out = A' @ B'^T + b_out via mma.sync m16n8k16 bf16 (HMMA).
// v2: CTA 128x128, 4 warps (2x2) of 64x64 -> halves redundant ldmatrix
// smem traffic (tensor:smem pipe ratio 8:1). Same K order => same
// numerics as verified R8/R9 version.
// =====================================================================
#define KCH      64
#define NCHUNKS  12
#define ROWB     144                      // (64+8) bf16 row stride in bytes
#define ABUF_SZ  (128 * ROWB)             // 18432 B
#define SAOFF(buf) ((buf) * ABUF_SZ)
#define SBOFF(buf) (2 * ABUF_SZ + (buf) * ABUF_SZ)
#define GEMM_SMEM (4 * ABUF_SZ)           // 73728 B

__global__ void __launch_bounds__(128, 2)
out_gemm_mma(const float* __restrict__ b_out, float* __restrict__ out) {
    extern __shared__ char smem[];
    uint32_t sb = smem_u32(smem);
    int tid = threadIdx.x;
    int wid = tid >> 5;           // 0..3
    int lane = tid & 31;
    int warp_m = wid >> 1;        // 0..1
    int warp_n = wid & 1;         // 0..1
    int m0 = blockIdx.y * 128;
    int n0 = blockIdx.x * 128;

    int g = lane >> 2;            // 0..7
    int t = lane & 3;             // 0..3

    auto issue = [&](int c, int buf) {
#pragma unroll
        for (int i = 0; i < 8; i++) {
            int f = tid + 128 * i;       // 0..1023
            int row = f >> 3;            // 0..127
            int q = f & 7;               // 0..7 (16B units)
            cpa16(sb + SAOFF(buf) + row * ROWB + q * 16,
                  &g_A2[(size_t)(m0 + row) * KP + c * KCH + q * 8]);
            cpa16(sb + SBOFF(buf) + row * ROWB + q * 16,
                  &g_B2[(size_t)(n0 + row) * KP + c * KCH + q * 8]);
        }
    };

    // verified lane formulas (R8), warp tiles now 64x64
    uint32_t a_lane = (uint32_t)((warp_m * 64 + (lane & 15)) * ROWB +
                                 ((lane >> 4) & 1) * 16);
    uint32_t b_lane = (uint32_t)((warp_n * 64 + (lane & 7) +
                                  ((lane >> 4) & 1) * 8) * ROWB +
                                 ((lane >> 3) & 1) * 16);

    float acc[4][8][4];
#pragma unroll
    for (int i = 0; i < 4; i++)
#pragma unroll
        for (int j = 0; j < 8; j++)
#pragma unroll
            for (int e = 0; e < 4; e++) acc[i][j][e] = 0.f;

    issue(0, 0);
    CPA_COMMIT();

    for (int c = 0; c < NCHUNKS; c++) {
        int buf = c & 1;
        CPA_WAIT0();
        __syncthreads();
        if (c + 1 < NCHUNKS) {
            issue(c + 1, buf ^ 1);
            CPA_COMMIT();
        }
        uint32_t abase = sb + SAOFF(buf) + a_lane;
        uint32_t bbase = sb + SBOFF(buf) + b_lane;
#pragma unroll
        for (int ks = 0; ks < 4; ks++) {
            uint32_t kb = (uint32_t)(ks * 32);   // 16 bf16 = 32 bytes
            uint32_t a[4][4];
#pragma unroll
            for (int mt = 0; mt < 4; mt++)
                ldsm4(abase + mt * 16 * ROWB + kb,
                      a[mt][0], a[mt][1], a[mt][2], a[mt][3]);
            uint32_t bq[8][2];
#pragma unroll
            for (int p = 0; p < 4; p++) {
                uint32_t r0, r1, r2, r3;
                ldsm4(bbase + p * 16 * ROWB + kb, r0, r1, r2, r3);
                bq[2 * p][0] = r0;     bq[2 * p][1] = r1;
                bq[2 * p + 1][0] = r2; bq[2 * p + 1][1] = r3;
            }
#pragma unroll
            for (int mt = 0; mt < 4; mt++)
#pragma unroll
                for (int nt = 0; nt < 8; nt++)
                    mma16816(acc[mt][nt], a[mt][0], a[mt][1], a[mt][2],
                             a[mt][3], bq[nt][0], bq[nt][1]);
        }
    }

#pragma unroll
    for (int mt = 0; mt < 4; mt++) {
        int r0 = m0 + warp_m * 64 + mt * 16 + g;
#pragma unroll
        for (int nt = 0; nt < 8; nt++) {
            int col = n0 + warp_n * 64 + nt * 8 + 2 * t;
            float2 bi = *reinterpret_cast<const float2*>(&b_out[col]);
            float2 o0 = {acc[mt][nt][0] + bi.x, acc[mt][nt][1] + bi.y};
            float2 o1 = {acc[mt][nt][2] + bi.x, acc[mt][nt][3] + bi.y};
            *reinterpret_cast<float2*>(&out[(size_t)r0 * VOCAB + col]) = o0;
            *reinterpret_cast<float2*>(&out[(size_t)(r0 + 8) * VOCAB + col]) = o1;
        }
    }
}

// =====================================================================
// launch
// =====================================================================
extern "C" void kernel_launch(void* const* d_in, const int* in_sizes, int n_in,
                              void* d_out, int out_size) {
    const int*   t     = (const int*)d_in[0];
    const float* emb   = (const float*)d_in[1];
    const float* h0    = (const float*)d_in[2];
    const float* w_ih  = (const float*)d_in[3];
    const float* w_hh  = (const float*)d_in[4];
    const float* b_ih  = (const float*)d_in[5];
    const float* b_hh  = (const float*)d_in[6];
    const float* w_out = (const float*)d_in[7];
    const float* b_out = (const float*)d_in[8];
    float* out = (float*)d_out;

    cudaFuncSetAttribute(out_gemm_mma,
                         cudaFuncAttributeMaxDynamicSharedMemorySize,
                         GEMM_SMEM);

    embed_gi_kernel<<<dim3(G3 / 64, MTOT / 64), 256>>>(t, emb, w_ih, b_ih);
    gru_kernel<<<TOT_NBLK, GRU_TPB>>>(h0, w_hh, b_hh, w_out);
    out_gemm_mma<<<dim3(VOCAB / 128, MTOT / 128), 128, GEMM_SMEM>>>(b_out, out);
}